// round 1
// baseline (speedup 1.0000x reference)
#include <cuda_runtime.h>
#include <math.h>

// Problem constants (fixed shapes)
#define Bz 512
#define Iz 512
#define Hz 1024
#define Oz 512
#define Tz 128

// Device scratch (allocation-free rule: __device__ globals)
__device__ float g_jx[Bz * Hz];                       // x@Wjx^T + bjx
__device__ float g_kx[Bz * Hz];                       // x@Wkx^T + bkx
__device__ float g_h0[Bz * Hz];                       // copy of h0
__device__ float g_hall[(size_t)Tz * Bz * Hz];        // all h_t, 256 MB

// ---------------------------------------------------------------------------
// Dual NT GEMM: acc1 = A[M,K] @ W1^T[N,K], acc2 = A @ W2^T.
// STEP=false: proj mode. A = x (ext), K = Iz. Writes g_jx/g_kx (+bias).
// STEP=true : recurrence. A = h_{t-1} (internal), K = Hz. Epilogue applies
//             sigmoid gates and writes h_t into g_hall[t].
// Tile: BM=64, BN=64, BK=16, 256 threads, 4x4 per thread, dual accumulators.
// ---------------------------------------------------------------------------
template <bool STEP>
__global__ void __launch_bounds__(256)
dual_gemm(const float* __restrict__ Aext,
          const float* __restrict__ W1, const float* __restrict__ W2,
          const float* __restrict__ b1, const float* __restrict__ b2,
          int K, int t)
{
    constexpr int BM = 64, BN = 64, BK = 16;
    __shared__ float As [BK][BM + 4];
    __shared__ float W1s[BK][BN + 4];
    __shared__ float W2s[BK][BN + 4];

    const float* A;
    if (STEP) {
        A = (t == 0) ? g_h0 : (g_hall + (size_t)(t - 1) * Bz * Hz);
    } else {
        A = Aext;
    }

    const int tid = threadIdx.x;
    const int m0 = blockIdx.y * BM;
    const int n0 = blockIdx.x * BN;

    // global-load mapping: 4 floats (one float4) per thread per tile
    const int lr = tid >> 2;            // 0..63 (row within tile)
    const int lk = (tid & 3) * 4;       // 0,4,8,12 (k within tile)

    // compute mapping: 16x16 thread grid, 4x4 per thread
    const int tmm = (tid & 15) * 4;
    const int tnn = (tid >> 4) * 4;

    float acc1[4][4] = {};
    float acc2[4][4] = {};

    for (int k0 = 0; k0 < K; k0 += BK) {
        float4 av = *(const float4*)(A  + (size_t)(m0 + lr) * K + k0 + lk);
        float4 w1 = *(const float4*)(W1 + (size_t)(n0 + lr) * K + k0 + lk);
        float4 w2 = *(const float4*)(W2 + (size_t)(n0 + lr) * K + k0 + lk);
        __syncthreads();   // previous iteration's consumers done
        As [lk + 0][lr] = av.x; As [lk + 1][lr] = av.y;
        As [lk + 2][lr] = av.z; As [lk + 3][lr] = av.w;
        W1s[lk + 0][lr] = w1.x; W1s[lk + 1][lr] = w1.y;
        W1s[lk + 2][lr] = w1.z; W1s[lk + 3][lr] = w1.w;
        W2s[lk + 0][lr] = w2.x; W2s[lk + 1][lr] = w2.y;
        W2s[lk + 2][lr] = w2.z; W2s[lk + 3][lr] = w2.w;
        __syncthreads();

        #pragma unroll
        for (int kk = 0; kk < BK; ++kk) {
            float a[4], u[4], v[4];
            #pragma unroll
            for (int i = 0; i < 4; ++i) a[i] = As[kk][tmm + i];
            #pragma unroll
            for (int j = 0; j < 4; ++j) { u[j] = W1s[kk][tnn + j]; v[j] = W2s[kk][tnn + j]; }
            #pragma unroll
            for (int i = 0; i < 4; ++i)
                #pragma unroll
                for (int j = 0; j < 4; ++j) {
                    acc1[i][j] = fmaf(a[i], u[j], acc1[i][j]);
                    acc2[i][j] = fmaf(a[i], v[j], acc2[i][j]);
                }
        }
    }

    if (STEP) {
        float* hout = g_hall + (size_t)t * Bz * Hz;
        #pragma unroll
        for (int i = 0; i < 4; ++i) {
            const int m = m0 + tmm + i;
            #pragma unroll
            for (int j = 0; j < 4; ++j) {
                const int n = n0 + tnn + j;
                const size_t idx = (size_t)m * Hz + n;
                const float hprev = A[idx];      // K == Hz, same layout
                const float pj = g_jx[idx] + acc1[i][j] + b1[n];
                const float pk = g_kx[idx] + acc2[i][j] + b2[n];
                const float jg = 1.0f / (1.0f + expf(-pj));
                const float kg = 1.0f / (1.0f + expf(-pk));
                hout[idx] = jg * (1.0f - hprev) + (1.0f - kg) * hprev;
            }
        }
    } else {
        #pragma unroll
        for (int i = 0; i < 4; ++i) {
            const int m = m0 + tmm + i;
            #pragma unroll
            for (int j = 0; j < 4; ++j) {
                const int n = n0 + tnn + j;
                const size_t idx = (size_t)m * Hz + n;
                g_jx[idx] = acc1[i][j] + b1[n];
                g_kx[idx] = acc2[i][j] + b2[n];
            }
        }
    }
}

// ---------------------------------------------------------------------------
// Batched output GEMM over all timesteps:
//   rows r = t*B + b of g_hall (shape [T*B, H]) times Wo^T[O, H] + bo.
//   out[b*T*O + t*O + o]
// Tile: BM=128, BN=64, BK=16, 256 threads, 8x4 per thread.
// ---------------------------------------------------------------------------
__global__ void __launch_bounds__(256)
out_gemm(const float* __restrict__ Wo, const float* __restrict__ bo,
         float* __restrict__ out)
{
    constexpr int BM = 128, BN = 64, BK = 16;
    __shared__ float As[BK][BM + 4];
    __shared__ float Ws[BK][BN + 4];

    const float* A = g_hall;   // [T*B, H] row-major
    const int tid = threadIdx.x;
    const int m0 = blockIdx.y * BM;
    const int n0 = blockIdx.x * BN;

    const int lr = tid >> 2;
    const int lk = (tid & 3) * 4;

    const int tmm = (tid >> 4) * 8;   // 0..120
    const int tnn = (tid & 15) * 4;   // 0..60

    float acc[8][4] = {};

    for (int k0 = 0; k0 < Hz; k0 += BK) {
        float4 a0 = *(const float4*)(A  + (size_t)(m0 + lr) * Hz + k0 + lk);
        float4 a1 = *(const float4*)(A  + (size_t)(m0 + 64 + lr) * Hz + k0 + lk);
        float4 w  = *(const float4*)(Wo + (size_t)(n0 + lr) * Hz + k0 + lk);
        __syncthreads();
        As[lk + 0][lr] = a0.x; As[lk + 1][lr] = a0.y;
        As[lk + 2][lr] = a0.z; As[lk + 3][lr] = a0.w;
        As[lk + 0][lr + 64] = a1.x; As[lk + 1][lr + 64] = a1.y;
        As[lk + 2][lr + 64] = a1.z; As[lk + 3][lr + 64] = a1.w;
        Ws[lk + 0][lr] = w.x; Ws[lk + 1][lr] = w.y;
        Ws[lk + 2][lr] = w.z; Ws[lk + 3][lr] = w.w;
        __syncthreads();

        #pragma unroll
        for (int kk = 0; kk < BK; ++kk) {
            float a[8], w4[4];
            #pragma unroll
            for (int i = 0; i < 8; ++i) a[i] = As[kk][tmm + i];
            #pragma unroll
            for (int j = 0; j < 4; ++j) w4[j] = Ws[kk][tnn + j];
            #pragma unroll
            for (int i = 0; i < 8; ++i)
                #pragma unroll
                for (int j = 0; j < 4; ++j)
                    acc[i][j] = fmaf(a[i], w4[j], acc[i][j]);
        }
    }

    #pragma unroll
    for (int i = 0; i < 8; ++i) {
        const int r = m0 + tmm + i;       // global row in [T*B)
        const int tt = r / Bz;
        const int bb = r % Bz;
        #pragma unroll
        for (int j = 0; j < 4; ++j) {
            const int n = n0 + tnn + j;
            out[(size_t)bb * Tz * Oz + (size_t)tt * Oz + n] = acc[i][j] + bo[n];
        }
    }
}

extern "C" void kernel_launch(void* const* d_in, const int* in_sizes, int n_in,
                              void* d_out, int out_size)
{
    const float* x   = (const float*)d_in[0];
    const float* h0  = (const float*)d_in[1];
    const float* Wjx = (const float*)d_in[2];
    const float* bjx = (const float*)d_in[3];
    const float* Wjh = (const float*)d_in[4];
    const float* bjh = (const float*)d_in[5];
    const float* Wkx = (const float*)d_in[6];
    const float* bkx = (const float*)d_in[7];
    const float* Wkh = (const float*)d_in[8];
    const float* bkh = (const float*)d_in[9];
    const float* Wo  = (const float*)d_in[10];
    const float* bo  = (const float*)d_in[11];
    float* out = (float*)d_out;

    // h0 -> device scratch
    cudaMemcpyToSymbolAsync(g_h0, h0, sizeof(float) * Bz * Hz, 0,
                            cudaMemcpyDeviceToDevice, 0);

    dim3 grid(Hz / 64, Bz / 64);   // (16, 8) = 128 CTAs

    // Time-invariant input projections (once)
    dual_gemm<false><<<grid, 256>>>(x, Wjx, Wkx, bjx, bkx, Iz, 0);

    // Sequential recurrence
    for (int t = 0; t < Tz; ++t)
        dual_gemm<true><<<grid, 256>>>(nullptr, Wjh, Wkh, bjh, bkh, Hz, t);

    // One batched output GEMM over all timesteps
    dim3 og(Oz / 64, (Tz * Bz) / 128);   // (8, 512)
    out_gemm<<<og, 256>>>(Wo, bo, out);

    // h_final = h_{T-1}
    cudaMemcpyFromSymbolAsync(out + (size_t)Bz * Tz * Oz, g_hall,
                              sizeof(float) * Bz * Hz,
                              sizeof(float) * (size_t)(Tz - 1) * Bz * Hz,
                              cudaMemcpyDeviceToDevice, 0);
}

// round 3
// speedup vs baseline: 3.5425x; 3.5425x over previous
#include <cuda_runtime.h>
#include <cstdint>

#define Bz 512
#define Iz 512
#define Hz 1024
#define Oz 512
#define Tz 128

// tcgen05 is arch-SPECIFIC (sm_103a). The harness also builds a generic
// compute_103 PTX pass where these instructions are illegal — guard them and
// give that pass compilable no-op fallbacks (it never runs on the GB300).
#if defined(__CUDA_ARCH__) && \
    (defined(__CUDA_ARCH_FEAT_SM103_ALL) || defined(__CUDA_ARCH_FEAT_SM100_ALL) || \
     defined(__CUDA_ARCH_SPECIFIC__))
#define HAS_TC5 1
#else
#define HAS_TC5 0
#endif

// --------------------------- device scratch ---------------------------------
__device__ float g_jx[Bz * Hz];                 // x@Wjx^T + bjx + bjh
__device__ float g_kx[Bz * Hz];                 // x@Wkx^T + bkx + bkh
__device__ float g_h0[Bz * Hz];
__device__ float g_hall[(size_t)Tz * Bz * Hz];  // all h_t (tf32-rounded), 256 MB
__device__ float g_Wjh[Hz * Hz];                // tf32-rounded weights
__device__ float g_Wkh[Hz * Hz];
__device__ float g_Wo[Oz * Hz];

// --------------------------- PTX helpers ------------------------------------
__device__ __forceinline__ uint32_t smem_u32(const void* p) {
    uint32_t a;
    asm("{ .reg .u64 t; cvta.to.shared.u64 t, %1; cvt.u32.u64 %0, t; }"
        : "=r"(a) : "l"(p));
    return a;
}
__device__ __forceinline__ float tf32r(float x) {
    uint32_t u; asm("cvt.rna.tf32.f32 %0, %1;" : "=r"(u) : "f"(x));
    return __uint_as_float(u);
}

#define CP16(dst, src) \
    asm volatile("cp.async.cg.shared.global [%0], [%1], 16;" :: "r"(dst), "l"(src) : "memory")
#define CP_COMMIT() asm volatile("cp.async.commit_group;" ::: "memory")
#define CP_WAIT(n)  asm volatile("cp.async.wait_group %0;" :: "n"(n) : "memory")
#define FENCE_ASYNC() asm volatile("fence.proxy.async.shared::cta;" ::: "memory")

#define MBAR_INIT(mb, cnt) \
    asm volatile("mbarrier.init.shared.b64 [%0], %1;" :: "r"(mb), "r"((uint32_t)(cnt)) : "memory")
#define MBAR_INVAL(mb) \
    asm volatile("mbarrier.inval.shared.b64 [%0];" :: "r"(mb) : "memory")

#define MBAR_WAIT(mb, par) do {                                                  \
    uint32_t _m = (mb), _p = (par), _d;                                          \
    asm volatile("{\n\t.reg .pred p;\n\t"                                        \
        "mbarrier.try_wait.parity.acquire.cta.shared::cta.b64 p, [%1], %2;\n\t"  \
        "selp.b32 %0, 1, 0, p;\n\t}" : "=r"(_d) : "r"(_m), "r"(_p) : "memory");  \
    if (!_d) {                                                                   \
        asm volatile("{\n\t.reg .pred P1;\n\t"                                   \
        "WL_%=:\n\t"                                                             \
        "mbarrier.try_wait.parity.acquire.cta.shared::cta.b64 P1, [%0], %1, 0x989680;\n\t" \
        "@P1 bra.uni WD_%=;\n\t"                                                 \
        "bra.uni WL_%=;\n\t"                                                     \
        "WD_%=:\n\t}" :: "r"(_m), "r"(_p) : "memory");                           \
    }                                                                            \
} while (0)

// ---- tcgen05 wrappers (guarded) ----
__device__ __forceinline__ void tc_alloc(uint32_t sa, uint32_t n) {
#if HAS_TC5
    asm volatile("tcgen05.alloc.cta_group::1.sync.aligned.shared::cta.b32 [%0], %1;"
                 :: "r"(sa), "r"(n) : "memory");
    asm volatile("tcgen05.relinquish_alloc_permit.cta_group::1.sync.aligned;");
#endif
}
__device__ __forceinline__ void tc_dealloc(uint32_t t, uint32_t n) {
#if HAS_TC5
    asm volatile("tcgen05.dealloc.cta_group::1.sync.aligned.b32 %0, %1;" :: "r"(t), "r"(n));
#endif
}
__device__ __forceinline__ void tc_commit(uint32_t mb) {
#if HAS_TC5
    asm volatile("tcgen05.commit.cta_group::1.mbarrier::arrive::one.shared::cluster.b64 [%0];"
                 :: "r"(mb) : "memory");
#endif
}
__device__ __forceinline__ void tc_fence_after() {
#if HAS_TC5
    asm volatile("tcgen05.fence::after_thread_sync;" ::: "memory");
#endif
}
__device__ __forceinline__ void tc_wait_ld() {
#if HAS_TC5
    asm volatile("tcgen05.wait::ld.sync.aligned;" ::: "memory");
#endif
}
__device__ __forceinline__ void tc_ld32(uint32_t* r, uint32_t ta) {
#if HAS_TC5
    asm volatile("tcgen05.ld.sync.aligned.32x32b.x32.b32 "
        "{%0, %1, %2, %3, %4, %5, %6, %7, %8, %9, %10, %11, %12, %13, %14, %15,"
        " %16, %17, %18, %19, %20, %21, %22, %23, %24, %25, %26, %27, %28, %29, %30, %31}, [%32];"
        : "=r"(r[0]),  "=r"(r[1]),  "=r"(r[2]),  "=r"(r[3]),
          "=r"(r[4]),  "=r"(r[5]),  "=r"(r[6]),  "=r"(r[7]),
          "=r"(r[8]),  "=r"(r[9]),  "=r"(r[10]), "=r"(r[11]),
          "=r"(r[12]), "=r"(r[13]), "=r"(r[14]), "=r"(r[15]),
          "=r"(r[16]), "=r"(r[17]), "=r"(r[18]), "=r"(r[19]),
          "=r"(r[20]), "=r"(r[21]), "=r"(r[22]), "=r"(r[23]),
          "=r"(r[24]), "=r"(r[25]), "=r"(r[26]), "=r"(r[27]),
          "=r"(r[28]), "=r"(r[29]), "=r"(r[30]), "=r"(r[31])
        : "r"(ta));
#else
    #pragma unroll
    for (int i = 0; i < 32; ++i) r[i] = 0;
#endif
}
__device__ __forceinline__ void mma_tf32(uint32_t d, uint64_t ad, uint64_t bd,
                                         uint32_t idesc, uint32_t en) {
#if HAS_TC5
    asm volatile(
        "{\n\t.reg .pred p;\n\tsetp.ne.u32 p, %5, 0;\n\t"
        "tcgen05.mma.cta_group::1.kind::tf32 [%0], %1, %2, %3, {%4, %4, %4, %4}, p;\n\t}"
        :: "r"(d), "l"(ad), "l"(bd), "r"(idesc), "r"(0u), "r"(en) : "memory");
#endif
}

// SW128 K-major smem descriptor (LBO=1, SBO=64, version=1)
__device__ __forceinline__ uint64_t mkdesc(uint32_t addr) {
    constexpr uint64_t BASE =
        (2ull << 61) | (1ull << 46) | (64ull << 32) | (1ull << 16);
    return BASE | ((uint64_t)(addr >> 4) & 0x3FFF);
}

__device__ __forceinline__ float sigm(float x) {
    return 1.0f / (1.0f + __expf(-x));
}

// --------------------------- weight rounding --------------------------------
__global__ void round_weights(const float* __restrict__ Wjh,
                              const float* __restrict__ Wkh,
                              const float* __restrict__ Wo) {
    for (int i = blockIdx.x * blockDim.x + threadIdx.x; i < Hz * Hz;
         i += gridDim.x * blockDim.x) {
        g_Wjh[i] = tf32r(Wjh[i]);
        g_Wkh[i] = tf32r(Wkh[i]);
        if (i < Oz * Hz) g_Wo[i] = tf32r(Wo[i]);
    }
}

// --------------------------- tensor-core GEMM -------------------------------
// STEP=true : NT=64.  D1 = h@Wjh^T, D2 = h@Wkh^T (TMEM cols [0,64), [64,128)).
//             Epilogue applies sigmoid gates, writes h_t (tf32-rounded).
// STEP=false: NT=128. D = g_hall@Wo^T. Epilogue adds bo, writes outputs.
template <int NT, bool STEP>
__global__ void __launch_bounds__(256, 1)
tc_gemm(const float* __restrict__ bo, float* __restrict__ outp, int t) {
    constexpr int KC = 64;            // k per chunk
    constexpr int NC = Hz / KC;       // 16 chunks
    constexpr uint32_t OFF_A  = 1024;
    constexpr uint32_t ABUF   = 128 * KC * 4;            // 32768
    constexpr uint32_t OFF_B1 = OFF_A + 2 * ABUF;        // 66560
    constexpr uint32_t BBUF   = NT * KC * 4;
    constexpr uint32_t OFF_B2 = OFF_B1 + 2 * BBUF;
    constexpr uint32_t IDESC =
        (8u << 24) | ((NT / 8) << 17) | (2u << 10) | (2u << 7) | (1u << 4);

    extern __shared__ char smem[];
    const uint32_t sb = smem_u32(smem);
    const int tid = threadIdx.x;
    const int wid = tid >> 5, lid = tid & 31;
    const int m0 = blockIdx.y * 128;
    const int n0 = blockIdx.x * NT;

    const float* Ag;
    if (STEP) Ag = (t == 0) ? g_h0 : g_hall + (size_t)(t - 1) * Bz * Hz;
    else      Ag = g_hall;
    const float* Arow = Ag + (size_t)m0 * Hz;
    const float* B1g = STEP ? g_Wjh : g_Wo;
    const float* B2g = g_Wkh;

    if (wid == 0) tc_alloc(sb + 0, 128);
    if (tid == 0) {
        #pragma unroll
        for (int c = 0; c < NC; ++c) MBAR_INIT(sb + 16 + 8 * c, 1);
    }
    __syncthreads();
    uint32_t tb;
    asm volatile("ld.shared.b32 %0, [%1];" : "=r"(tb) : "r"(sb + 0));

    // ---- chunk loader (cp.async, SW128-swizzled smem) ----
    auto load_chunk = [&](int c) {
        const int b = c & 1;
        const int k0 = c * KC;
        const uint32_t a_s = sb + OFF_A + b * ABUF;
        #pragma unroll
        for (int i = 0; i < 8; ++i) {                  // A: 128 rows x 64 f
            int v = i * 256 + tid;
            int row = v >> 4, kk = (v & 15) << 2;
            uint32_t off = (uint32_t)(row << 7) + ((kk & 31) << 2);
            off ^= (off >> 3) & 0x70;
            CP16(a_s + (uint32_t)((kk >> 5) * 16384) + off,
                 Arow + (size_t)row * Hz + k0 + kk);
        }
        const uint32_t b1_s = sb + OFF_B1 + b * BBUF;
        #pragma unroll
        for (int i = 0; i < NT / 16; ++i) {            // B: NT rows x 64 f
            int v = i * 256 + tid;
            int row = v >> 4, kk = (v & 15) << 2;
            uint32_t off = (uint32_t)(row << 7) + ((kk & 31) << 2);
            off ^= (off >> 3) & 0x70;
            uint32_t so = (uint32_t)((kk >> 5) * (NT * 128)) + off;
            const size_t gidx = (size_t)(n0 + row) * Hz + k0 + kk;
            CP16(b1_s + so, B1g + gidx);
            if (STEP) CP16(sb + OFF_B2 + b * BBUF + so, B2g + gidx);
        }
        CP_COMMIT();
    };

    load_chunk(0);
    for (int c = 0; c < NC; ++c) {
        const int b = c & 1;
        if (c + 1 < NC) {
            if (c >= 1) MBAR_WAIT(sb + 16 + 8 * (c - 1), 0);  // buffer free
            load_chunk(c + 1);
            CP_WAIT(1);
        } else {
            CP_WAIT(0);
        }
        FENCE_ASYNC();
        __syncthreads();
        if (tid == 0) {
            uint64_t ad  = mkdesc(sb + OFF_A  + b * ABUF);
            uint64_t bd1 = mkdesc(sb + OFF_B1 + b * BBUF);
            uint64_t bd2 = STEP ? mkdesc(sb + OFF_B2 + b * BBUF) : 0;
            #pragma unroll
            for (int s = 0; s < 2; ++s)
                #pragma unroll
                for (int q = 0; q < 4; ++q) {
                    uint32_t en = (c | s | q) != 0;
                    uint64_t ao = ad + s * 1024 + q * 2;
                    mma_tf32(tb, ao, bd1 + s * (NT * 8) + q * 2, IDESC, en);
                    if (STEP)
                        mma_tf32(tb + NT, ao, bd2 + s * (NT * 8) + q * 2, IDESC, en);
                }
            tc_commit(sb + 16 + 8 * c);
        }
    }

    // ---- wait for all MMAs (last chunk's commit covers all prior) ----
    MBAR_WAIT(sb + 16 + 8 * (NC - 1), 0);
    tc_fence_after();

    const int sub = wid & 3, wg = wid >> 2;
    const int m = m0 + sub * 32 + lid;

    if (STEP) {
        float* hout = g_hall + (size_t)t * Bz * Hz;
        const int nl = wg * 32;                 // n-local 0 or 32
        uint32_t jr[32], kr[32];
        tc_ld32(jr, tb + nl);
        tc_ld32(kr, tb + NT + nl);
        tc_wait_ld();
        const int n = n0 + nl;
        const float4* jx4 = (const float4*)(g_jx + (size_t)m * Hz + n);
        const float4* kx4 = (const float4*)(g_kx + (size_t)m * Hz + n);
        const float4* hp4 = (const float4*)(Ag   + (size_t)m * Hz + n);
        float4* ho4 = (float4*)(hout + (size_t)m * Hz + n);
        #pragma unroll
        for (int v = 0; v < 8; ++v) {
            float4 jx = jx4[v], kx = kx4[v], hp = hp4[v], o;
            {
                float jg = sigm(jx.x + __uint_as_float(jr[4 * v + 0]));
                float kg = sigm(kx.x + __uint_as_float(kr[4 * v + 0]));
                o.x = tf32r(jg + hp.x * (1.0f - jg - kg));
            }
            {
                float jg = sigm(jx.y + __uint_as_float(jr[4 * v + 1]));
                float kg = sigm(kx.y + __uint_as_float(kr[4 * v + 1]));
                o.y = tf32r(jg + hp.y * (1.0f - jg - kg));
            }
            {
                float jg = sigm(jx.z + __uint_as_float(jr[4 * v + 2]));
                float kg = sigm(kx.z + __uint_as_float(kr[4 * v + 2]));
                o.z = tf32r(jg + hp.z * (1.0f - jg - kg));
            }
            {
                float jg = sigm(jx.w + __uint_as_float(jr[4 * v + 3]));
                float kg = sigm(kx.w + __uint_as_float(kr[4 * v + 3]));
                o.w = tf32r(jg + hp.w * (1.0f - jg - kg));
            }
            ho4[v] = o;
        }
    } else {
        const int tt = m >> 9;                  // m / Bz
        const int bb = m & (Bz - 1);
        float* orow = outp + (size_t)bb * Tz * Oz + (size_t)tt * Oz;
        #pragma unroll
        for (int g = 0; g < 2; ++g) {
            const int nl = wg * 64 + g * 32;
            uint32_t r[32];
            tc_ld32(r, tb + nl);
            tc_wait_ld();
            const int n = n0 + nl;
            const float4* bo4 = (const float4*)(bo + n);
            float4* op = (float4*)(orow + n);
            #pragma unroll
            for (int v = 0; v < 8; ++v) {
                float4 b4 = bo4[v], o;
                o.x = __uint_as_float(r[4 * v + 0]) + b4.x;
                o.y = __uint_as_float(r[4 * v + 1]) + b4.y;
                o.z = __uint_as_float(r[4 * v + 2]) + b4.z;
                o.w = __uint_as_float(r[4 * v + 3]) + b4.w;
                op[v] = o;
            }
        }
    }

    __syncthreads();
    if (tid == 0) {
        #pragma unroll
        for (int c = 0; c < NC; ++c) MBAR_INVAL(sb + 16 + 8 * c);
    }
    __syncthreads();
    if (wid == 0) tc_dealloc(tb, 128);
}

// --------------------------- SIMT projection (once) -------------------------
__global__ void __launch_bounds__(256)
proj_gemm(const float* __restrict__ x,
          const float* __restrict__ W1, const float* __restrict__ W2,
          const float* __restrict__ b1a, const float* __restrict__ b1b,
          const float* __restrict__ b2a, const float* __restrict__ b2b) {
    constexpr int BM = 64, BN = 64, BK = 16, K = Iz;
    __shared__ float As[BK][BM + 4];
    __shared__ float W1s[BK][BN + 4];
    __shared__ float W2s[BK][BN + 4];

    const int tid = threadIdx.x;
    const int m0 = blockIdx.y * BM;
    const int n0 = blockIdx.x * BN;
    const int lr = tid >> 2;
    const int lk = (tid & 3) * 4;
    const int tmm = (tid & 15) * 4;
    const int tnn = (tid >> 4) * 4;

    float acc1[4][4] = {};
    float acc2[4][4] = {};

    for (int k0 = 0; k0 < K; k0 += BK) {
        float4 av = *(const float4*)(x  + (size_t)(m0 + lr) * K + k0 + lk);
        float4 w1 = *(const float4*)(W1 + (size_t)(n0 + lr) * K + k0 + lk);
        float4 w2 = *(const float4*)(W2 + (size_t)(n0 + lr) * K + k0 + lk);
        __syncthreads();
        As [lk + 0][lr] = av.x; As [lk + 1][lr] = av.y;
        As [lk + 2][lr] = av.z; As [lk + 3][lr] = av.w;
        W1s[lk + 0][lr] = w1.x; W1s[lk + 1][lr] = w1.y;
        W1s[lk + 2][lr] = w1.z; W1s[lk + 3][lr] = w1.w;
        W2s[lk + 0][lr] = w2.x; W2s[lk + 1][lr] = w2.y;
        W2s[lk + 2][lr] = w2.z; W2s[lk + 3][lr] = w2.w;
        __syncthreads();
        #pragma unroll
        for (int kk = 0; kk < BK; ++kk) {
            float a[4], u[4], v[4];
            #pragma unroll
            for (int i = 0; i < 4; ++i) a[i] = As[kk][tmm + i];
            #pragma unroll
            for (int j = 0; j < 4; ++j) { u[j] = W1s[kk][tnn + j]; v[j] = W2s[kk][tnn + j]; }
            #pragma unroll
            for (int i = 0; i < 4; ++i)
                #pragma unroll
                for (int j = 0; j < 4; ++j) {
                    acc1[i][j] = fmaf(a[i], u[j], acc1[i][j]);
                    acc2[i][j] = fmaf(a[i], v[j], acc2[i][j]);
                }
        }
    }

    #pragma unroll
    for (int i = 0; i < 4; ++i) {
        const int m = m0 + tmm + i;
        #pragma unroll
        for (int j = 0; j < 4; ++j) {
            const int n = n0 + tnn + j;
            const size_t idx = (size_t)m * Hz + n;
            g_jx[idx] = acc1[i][j] + b1a[n] + b1b[n];   // fold bjx + bjh
            g_kx[idx] = acc2[i][j] + b2a[n] + b2b[n];   // fold bkx + bkh
        }
    }
}

// --------------------------- host launcher ----------------------------------
extern "C" void kernel_launch(void* const* d_in, const int* in_sizes, int n_in,
                              void* d_out, int out_size) {
    const float* x   = (const float*)d_in[0];
    const float* h0  = (const float*)d_in[1];
    const float* Wjx = (const float*)d_in[2];
    const float* bjx = (const float*)d_in[3];
    const float* Wjh = (const float*)d_in[4];
    const float* bjh = (const float*)d_in[5];
    const float* Wkx = (const float*)d_in[6];
    const float* bkx = (const float*)d_in[7];
    const float* Wkh = (const float*)d_in[8];
    const float* bkh = (const float*)d_in[9];
    const float* Wo  = (const float*)d_in[10];
    const float* bo  = (const float*)d_in[11];
    float* out = (float*)d_out;

    cudaMemcpyToSymbolAsync(g_h0, h0, sizeof(float) * Bz * Hz, 0,
                            cudaMemcpyDeviceToDevice, 0);

    round_weights<<<512, 256>>>(Wjh, Wkh, Wo);
    proj_gemm<<<dim3(Hz / 64, Bz / 64), 256>>>(x, Wjx, Wkx, bjx, bjh, bkx, bkh);

    constexpr int SME = 132096;
    cudaFuncSetAttribute(tc_gemm<64, true>,
                         cudaFuncAttributeMaxDynamicSharedMemorySize, SME);
    cudaFuncSetAttribute(tc_gemm<128, false>,
                         cudaFuncAttributeMaxDynamicSharedMemorySize, SME);

    for (int t = 0; t < Tz; ++t)
        tc_gemm<64, true><<<dim3(Hz / 64, Bz / 128), 256, SME>>>(nullptr, nullptr, t);

    tc_gemm<128, false><<<dim3(Oz / 128, (Tz * Bz) / 128), 256, SME>>>(bo, out, 0);

    cudaMemcpyFromSymbolAsync(out + (size_t)Bz * Tz * Oz, g_hall,
                              sizeof(float) * Bz * Hz,
                              sizeof(float) * (size_t)(Tz - 1) * Bz * Hz,
                              cudaMemcpyDeviceToDevice, 0);
}

// round 4
// speedup vs baseline: 3.8623x; 1.0903x over previous
#include <cuda_runtime.h>
#include <cstdint>

#define Bz 512
#define Iz 512
#define Hz 1024
#define Oz 512
#define Tz 128

// tcgen05 is arch-SPECIFIC (sm_103a). The harness also builds a generic
// compute_103 PTX pass where these instructions are illegal — guard them.
#if defined(__CUDA_ARCH__) && \
    (defined(__CUDA_ARCH_FEAT_SM103_ALL) || defined(__CUDA_ARCH_FEAT_SM100_ALL) || \
     defined(__CUDA_ARCH_SPECIFIC__))
#define HAS_TC5 1
#else
#define HAS_TC5 0
#endif

// --------------------------- device scratch ---------------------------------
__device__ float g_jx[Bz * Hz];                 // x@Wjx^T + bjx + bjh
__device__ float g_kx[Bz * Hz];                 // x@Wkx^T + bkx + bkh
__device__ float g_h0[Bz * Hz];
__device__ float g_hall[(size_t)Tz * Bz * Hz];  // all h_t (tf32-rounded), 256 MB
__device__ float g_Wjh[Hz * Hz];                // tf32-rounded weights
__device__ float g_Wkh[Hz * Hz];
__device__ float g_Wo[Oz * Hz];

// --------------------------- PTX helpers ------------------------------------
__device__ __forceinline__ uint32_t smem_u32(const void* p) {
    uint32_t a;
    asm("{ .reg .u64 t; cvta.to.shared.u64 t, %1; cvt.u32.u64 %0, t; }"
        : "=r"(a) : "l"(p));
    return a;
}
__device__ __forceinline__ float tf32r(float x) {
    uint32_t u; asm("cvt.rna.tf32.f32 %0, %1;" : "=r"(u) : "f"(x));
    return __uint_as_float(u);
}

#define CP16(dst, src) \
    asm volatile("cp.async.cg.shared.global [%0], [%1], 16;" :: "r"(dst), "l"(src) : "memory")
// This thread's prior cp.asyncs arrive (count 1) on mbar when they complete.
#define CPA_ARRIVE(mb) \
    asm volatile("cp.async.mbarrier.arrive.noinc.shared::cta.b64 [%0];" :: "r"(mb) : "memory")
#define FENCE_ASYNC() asm volatile("fence.proxy.async.shared::cta;" ::: "memory")

#define MBAR_INIT(mb, cnt) \
    asm volatile("mbarrier.init.shared.b64 [%0], %1;" :: "r"(mb), "r"((uint32_t)(cnt)) : "memory")
#define MBAR_INVAL(mb) \
    asm volatile("mbarrier.inval.shared.b64 [%0];" :: "r"(mb) : "memory")

#define MBAR_WAIT(mb, par) do {                                                  \
    uint32_t _m = (mb), _p = (par), _d;                                          \
    asm volatile("{\n\t.reg .pred p;\n\t"                                        \
        "mbarrier.try_wait.parity.acquire.cta.shared::cta.b64 p, [%1], %2;\n\t"  \
        "selp.b32 %0, 1, 0, p;\n\t}" : "=r"(_d) : "r"(_m), "r"(_p) : "memory");  \
    if (!_d) {                                                                   \
        asm volatile("{\n\t.reg .pred P1;\n\t"                                   \
        "WL_%=:\n\t"                                                             \
        "mbarrier.try_wait.parity.acquire.cta.shared::cta.b64 P1, [%0], %1, 0x989680;\n\t" \
        "@P1 bra.uni WD_%=;\n\t"                                                 \
        "bra.uni WL_%=;\n\t"                                                     \
        "WD_%=:\n\t}" :: "r"(_m), "r"(_p) : "memory");                           \
    }                                                                            \
} while (0)

// ---- tcgen05 wrappers (guarded) ----
__device__ __forceinline__ void tc_alloc(uint32_t sa, uint32_t n) {
#if HAS_TC5
    asm volatile("tcgen05.alloc.cta_group::1.sync.aligned.shared::cta.b32 [%0], %1;"
                 :: "r"(sa), "r"(n) : "memory");
    asm volatile("tcgen05.relinquish_alloc_permit.cta_group::1.sync.aligned;");
#endif
}
__device__ __forceinline__ void tc_dealloc(uint32_t t, uint32_t n) {
#if HAS_TC5
    asm volatile("tcgen05.dealloc.cta_group::1.sync.aligned.b32 %0, %1;" :: "r"(t), "r"(n));
#endif
}
__device__ __forceinline__ void tc_commit(uint32_t mb) {
#if HAS_TC5
    asm volatile("tcgen05.commit.cta_group::1.mbarrier::arrive::one.shared::cluster.b64 [%0];"
                 :: "r"(mb) : "memory");
#endif
}
__device__ __forceinline__ void tc_fence_after() {
#if HAS_TC5
    asm volatile("tcgen05.fence::after_thread_sync;" ::: "memory");
#endif
}
__device__ __forceinline__ void tc_wait_ld() {
#if HAS_TC5
    asm volatile("tcgen05.wait::ld.sync.aligned;" ::: "memory");
#endif
}
__device__ __forceinline__ void tc_ld32(uint32_t* r, uint32_t ta) {
#if HAS_TC5
    asm volatile("tcgen05.ld.sync.aligned.32x32b.x32.b32 "
        "{%0, %1, %2, %3, %4, %5, %6, %7, %8, %9, %10, %11, %12, %13, %14, %15,"
        " %16, %17, %18, %19, %20, %21, %22, %23, %24, %25, %26, %27, %28, %29, %30, %31}, [%32];"
        : "=r"(r[0]),  "=r"(r[1]),  "=r"(r[2]),  "=r"(r[3]),
          "=r"(r[4]),  "=r"(r[5]),  "=r"(r[6]),  "=r"(r[7]),
          "=r"(r[8]),  "=r"(r[9]),  "=r"(r[10]), "=r"(r[11]),
          "=r"(r[12]), "=r"(r[13]), "=r"(r[14]), "=r"(r[15]),
          "=r"(r[16]), "=r"(r[17]), "=r"(r[18]), "=r"(r[19]),
          "=r"(r[20]), "=r"(r[21]), "=r"(r[22]), "=r"(r[23]),
          "=r"(r[24]), "=r"(r[25]), "=r"(r[26]), "=r"(r[27]),
          "=r"(r[28]), "=r"(r[29]), "=r"(r[30]), "=r"(r[31])
        : "r"(ta));
#else
    #pragma unroll
    for (int i = 0; i < 32; ++i) r[i] = 0;
#endif
}
__device__ __forceinline__ void mma_tf32(uint32_t d, uint64_t ad, uint64_t bd,
                                         uint32_t idesc, uint32_t en) {
#if HAS_TC5
    asm volatile(
        "{\n\t.reg .pred p;\n\tsetp.ne.u32 p, %5, 0;\n\t"
        "tcgen05.mma.cta_group::1.kind::tf32 [%0], %1, %2, %3, {%4, %4, %4, %4}, p;\n\t}"
        :: "r"(d), "l"(ad), "l"(bd), "r"(idesc), "r"(0u), "r"(en) : "memory");
#endif
}

// SW128 K-major smem descriptor (LBO=1, SBO=64, version=1)
__device__ __forceinline__ uint64_t mkdesc(uint32_t addr) {
    constexpr uint64_t BASE =
        (2ull << 61) | (1ull << 46) | (64ull << 32) | (1ull << 16);
    return BASE | ((uint64_t)(addr >> 4) & 0x3FFF);
}

__device__ __forceinline__ float sigm(float x) {
    return 1.0f / (1.0f + __expf(-x));
}

// --------------------------- weight rounding --------------------------------
__global__ void round_weights(const float* __restrict__ Wjh,
                              const float* __restrict__ Wkh,
                              const float* __restrict__ Wo) {
    for (int i = blockIdx.x * blockDim.x + threadIdx.x; i < Hz * Hz;
         i += gridDim.x * blockDim.x) {
        g_Wjh[i] = tf32r(Wjh[i]);
        g_Wkh[i] = tf32r(Wkh[i]);
        if (i < Oz * Hz) g_Wo[i] = tf32r(Wo[i]);
    }
}

// --------------------------- tensor-core GEMM -------------------------------
// Producer/consumer pipeline: 256 producer threads (cp.async -> full[s]
// mbarrier), 1 MMA thread (tid 256: full wait -> MMA -> commit -> empty[s]).
// 3 stages x 64KB. No __syncthreads in the mainloop.
// STEP=true : NT=64.  D1 = h@Wjh^T, D2 = h@Wkh^T. Gates fused in epilogue.
// STEP=false: NT=128. D = g_hall@Wo^T + bo.
template <int NT, bool STEP>
__global__ void __launch_bounds__(288, 1)
tc_gemm(const float* __restrict__ bo, float* __restrict__ outp, int t) {
    constexpr int KC = 64;            // k per chunk
    constexpr int NC = Hz / KC;       // 16 chunks
    constexpr int S  = 3;             // pipeline stages
    constexpr uint32_t STG = 65536;   // stage bytes: A 32K + B 32K
    constexpr uint32_t OFF = 1024;
    constexpr uint32_t IDESC =
        (8u << 24) | ((NT / 8) << 17) | (2u << 10) | (2u << 7) | (1u << 4);

    extern __shared__ char smem[];
    const uint32_t sb = smem_u32(smem);
    const int tid = threadIdx.x;
    const int wid = tid >> 5, lid = tid & 31;
    const int m0 = blockIdx.y * 128;
    const int n0 = blockIdx.x * NT;

    const float* Ag;
    if (STEP) Ag = (t == 0) ? g_h0 : g_hall + (size_t)(t - 1) * Bz * Hz;
    else      Ag = g_hall;
    const float* Arow = Ag + (size_t)m0 * Hz;
    const float* B1g = STEP ? g_Wjh : g_Wo;
    const float* B2g = g_Wkh;

    // barriers: full[s] at sb+16+16s (count 256), empty[s] at sb+24+16s (count 1)
    if (wid == 0) tc_alloc(sb + 0, 128);
    if (tid == 0) {
        #pragma unroll
        for (int s = 0; s < S; ++s) {
            MBAR_INIT(sb + 16 + 16 * s, 256);
            MBAR_INIT(sb + 24 + 16 * s, 1);
        }
    }
    __syncthreads();
    uint32_t tb;
    asm volatile("ld.shared.b32 %0, [%1];" : "=r"(tb) : "r"(sb + 0));

    if (tid < 256) {
        // ------------------ producers ------------------
        for (int c = 0; c < NC; ++c) {
            const int s = c % S;
            if (c >= S) MBAR_WAIT(sb + 24 + 16 * s, ((c / S) - 1) & 1);
            const uint32_t base = sb + OFF + s * STG;
            const int k0 = c * KC;
            #pragma unroll
            for (int i = 0; i < 8; ++i) {                 // A: 128 x 64 f32
                int v = i * 256 + tid;
                int row = v >> 4, kk = (v & 15) << 2;
                uint32_t off = (uint32_t)(row << 7) + ((kk & 31) << 2);
                off ^= (off >> 3) & 0x70;
                CP16(base + (uint32_t)((kk >> 5) * 16384) + off,
                     Arow + (size_t)row * Hz + k0 + kk);
            }
            #pragma unroll
            for (int i = 0; i < NT / 16; ++i) {           // B: NT x 64 f32
                int v = i * 256 + tid;
                int row = v >> 4, kk = (v & 15) << 2;
                uint32_t off = (uint32_t)(row << 7) + ((kk & 31) << 2);
                off ^= (off >> 3) & 0x70;
                uint32_t so = (uint32_t)((kk >> 5) * (NT * 128)) + off;
                const size_t gidx = (size_t)(n0 + row) * Hz + k0 + kk;
                CP16(base + 32768 + so, B1g + gidx);
                if (STEP) CP16(base + 49152 + so, B2g + gidx);
            }
            CPA_ARRIVE(sb + 16 + 16 * s);
        }
    } else if (tid == 256) {
        // ------------------ MMA issuer ------------------
        for (int c = 0; c < NC; ++c) {
            const int s = c % S;
            MBAR_WAIT(sb + 16 + 16 * s, (c / S) & 1);
            FENCE_ASYNC();
            const uint32_t base = sb + OFF + s * STG;
            const uint64_t ad  = mkdesc(base);
            const uint64_t bd1 = mkdesc(base + 32768);
            const uint64_t bd2 = mkdesc(base + 49152);
            #pragma unroll
            for (int h = 0; h < 2; ++h)
                #pragma unroll
                for (int q = 0; q < 4; ++q) {
                    uint32_t en = (c | h | q) != 0;
                    uint64_t ao = ad + h * 1024 + q * 2;
                    mma_tf32(tb, ao, bd1 + h * (NT * 8) + q * 2, IDESC, en);
                    if (STEP)
                        mma_tf32(tb + NT, ao, bd2 + h * (NT * 8) + q * 2, IDESC, en);
                }
            tc_commit(sb + 24 + 16 * s);
        }
    }

    // all MMAs done <=> last chunk's empty barrier completed its final phase
    MBAR_WAIT(sb + 24 + 16 * ((NC - 1) % S), ((NC - 1) / S) & 1);
    tc_fence_after();

    if (wid < 8) {
        const int sub = wid & 3, wg = wid >> 2;
        const int m = m0 + sub * 32 + lid;

        if (STEP) {
            float* hout = g_hall + (size_t)t * Bz * Hz;
            const int nl = wg * 32;
            uint32_t jr[32], kr[32];
            tc_ld32(jr, tb + nl);
            tc_ld32(kr, tb + NT + nl);
            tc_wait_ld();
            const int n = n0 + nl;
            const float4* jx4 = (const float4*)(g_jx + (size_t)m * Hz + n);
            const float4* kx4 = (const float4*)(g_kx + (size_t)m * Hz + n);
            const float4* hp4 = (const float4*)(Ag   + (size_t)m * Hz + n);
            float4* ho4 = (float4*)(hout + (size_t)m * Hz + n);
            #pragma unroll
            for (int v = 0; v < 8; ++v) {
                float4 jx = jx4[v], kx = kx4[v], hp = hp4[v], o;
                {
                    float jg = sigm(jx.x + __uint_as_float(jr[4 * v + 0]));
                    float kg = sigm(kx.x + __uint_as_float(kr[4 * v + 0]));
                    o.x = tf32r(jg + hp.x * (1.0f - jg - kg));
                }
                {
                    float jg = sigm(jx.y + __uint_as_float(jr[4 * v + 1]));
                    float kg = sigm(kx.y + __uint_as_float(kr[4 * v + 1]));
                    o.y = tf32r(jg + hp.y * (1.0f - jg - kg));
                }
                {
                    float jg = sigm(jx.z + __uint_as_float(jr[4 * v + 2]));
                    float kg = sigm(kx.z + __uint_as_float(kr[4 * v + 2]));
                    o.z = tf32r(jg + hp.z * (1.0f - jg - kg));
                }
                {
                    float jg = sigm(jx.w + __uint_as_float(jr[4 * v + 3]));
                    float kg = sigm(kx.w + __uint_as_float(kr[4 * v + 3]));
                    o.w = tf32r(jg + hp.w * (1.0f - jg - kg));
                }
                ho4[v] = o;
            }
        } else {
            const int tt = m >> 9;
            const int bb = m & (Bz - 1);
            float* orow = outp + (size_t)bb * Tz * Oz + (size_t)tt * Oz;
            #pragma unroll
            for (int g = 0; g < 2; ++g) {
                const int nl = wg * 64 + g * 32;
                uint32_t r[32];
                tc_ld32(r, tb + nl);
                tc_wait_ld();
                const int n = n0 + nl;
                const float4* bo4 = (const float4*)(bo + n);
                float4* op = (float4*)(orow + n);
                #pragma unroll
                for (int v = 0; v < 8; ++v) {
                    float4 b4 = bo4[v], o;
                    o.x = __uint_as_float(r[4 * v + 0]) + b4.x;
                    o.y = __uint_as_float(r[4 * v + 1]) + b4.y;
                    o.z = __uint_as_float(r[4 * v + 2]) + b4.z;
                    o.w = __uint_as_float(r[4 * v + 3]) + b4.w;
                    op[v] = o;
                }
            }
        }
    }

    __syncthreads();
    if (tid == 0) {
        #pragma unroll
        for (int s = 0; s < S; ++s) {
            MBAR_INVAL(sb + 16 + 16 * s);
            MBAR_INVAL(sb + 24 + 16 * s);
        }
    }
    __syncthreads();
    if (wid == 0) tc_dealloc(tb, 128);
}

// --------------------------- SIMT projection (once) -------------------------
__global__ void __launch_bounds__(256)
proj_gemm(const float* __restrict__ x,
          const float* __restrict__ W1, const float* __restrict__ W2,
          const float* __restrict__ b1a, const float* __restrict__ b1b,
          const float* __restrict__ b2a, const float* __restrict__ b2b) {
    constexpr int BM = 64, BN = 64, BK = 16, K = Iz;
    __shared__ float As[BK][BM + 4];
    __shared__ float W1s[BK][BN + 4];
    __shared__ float W2s[BK][BN + 4];

    const int tid = threadIdx.x;
    const int m0 = blockIdx.y * BM;
    const int n0 = blockIdx.x * BN;
    const int lr = tid >> 2;
    const int lk = (tid & 3) * 4;
    const int tmm = (tid & 15) * 4;
    const int tnn = (tid >> 4) * 4;

    float acc1[4][4] = {};
    float acc2[4][4] = {};

    for (int k0 = 0; k0 < K; k0 += BK) {
        float4 av = *(const float4*)(x  + (size_t)(m0 + lr) * K + k0 + lk);
        float4 w1 = *(const float4*)(W1 + (size_t)(n0 + lr) * K + k0 + lk);
        float4 w2 = *(const float4*)(W2 + (size_t)(n0 + lr) * K + k0 + lk);
        __syncthreads();
        As [lk + 0][lr] = av.x; As [lk + 1][lr] = av.y;
        As [lk + 2][lr] = av.z; As [lk + 3][lr] = av.w;
        W1s[lk + 0][lr] = w1.x; W1s[lk + 1][lr] = w1.y;
        W1s[lk + 2][lr] = w1.z; W1s[lk + 3][lr] = w1.w;
        W2s[lk + 0][lr] = w2.x; W2s[lk + 1][lr] = w2.y;
        W2s[lk + 2][lr] = w2.z; W2s[lk + 3][lr] = w2.w;
        __syncthreads();
        #pragma unroll
        for (int kk = 0; kk < BK; ++kk) {
            float a[4], u[4], v[4];
            #pragma unroll
            for (int i = 0; i < 4; ++i) a[i] = As[kk][tmm + i];
            #pragma unroll
            for (int j = 0; j < 4; ++j) { u[j] = W1s[kk][tnn + j]; v[j] = W2s[kk][tnn + j]; }
            #pragma unroll
            for (int i = 0; i < 4; ++i)
                #pragma unroll
                for (int j = 0; j < 4; ++j) {
                    acc1[i][j] = fmaf(a[i], u[j], acc1[i][j]);
                    acc2[i][j] = fmaf(a[i], v[j], acc2[i][j]);
                }
        }
    }

    #pragma unroll
    for (int i = 0; i < 4; ++i) {
        const int m = m0 + tmm + i;
        #pragma unroll
        for (int j = 0; j < 4; ++j) {
            const int n = n0 + tnn + j;
            const size_t idx = (size_t)m * Hz + n;
            g_jx[idx] = acc1[i][j] + b1a[n] + b1b[n];   // fold bjx + bjh
            g_kx[idx] = acc2[i][j] + b2a[n] + b2b[n];   // fold bkx + bkh
        }
    }
}

// --------------------------- host launcher ----------------------------------
extern "C" void kernel_launch(void* const* d_in, const int* in_sizes, int n_in,
                              void* d_out, int out_size) {
    const float* x   = (const float*)d_in[0];
    const float* h0  = (const float*)d_in[1];
    const float* Wjx = (const float*)d_in[2];
    const float* bjx = (const float*)d_in[3];
    const float* Wjh = (const float*)d_in[4];
    const float* bjh = (const float*)d_in[5];
    const float* Wkx = (const float*)d_in[6];
    const float* bkx = (const float*)d_in[7];
    const float* Wkh = (const float*)d_in[8];
    const float* bkh = (const float*)d_in[9];
    const float* Wo  = (const float*)d_in[10];
    const float* bo  = (const float*)d_in[11];
    float* out = (float*)d_out;

    cudaMemcpyToSymbolAsync(g_h0, h0, sizeof(float) * Bz * Hz, 0,
                            cudaMemcpyDeviceToDevice, 0);

    round_weights<<<512, 256>>>(Wjh, Wkh, Wo);
    proj_gemm<<<dim3(Hz / 64, Bz / 64), 256>>>(x, Wjx, Wkx, bjx, bjh, bkx, bkh);

    constexpr int SME = 1024 + 3 * 65536;   // 197632
    cudaFuncSetAttribute(tc_gemm<64, true>,
                         cudaFuncAttributeMaxDynamicSharedMemorySize, SME);
    cudaFuncSetAttribute(tc_gemm<128, false>,
                         cudaFuncAttributeMaxDynamicSharedMemorySize, SME);

    for (int t = 0; t < Tz; ++t)
        tc_gemm<64, true><<<dim3(Hz / 64, Bz / 128), 288, SME>>>(nullptr, nullptr, t);

    tc_gemm<128, false><<<dim3(Oz / 128, (Tz * Bz) / 128), 288, SME>>>(bo, out, 0);

    cudaMemcpyFromSymbolAsync(out + (size_t)Bz * Tz * Oz, g_hall,
                              sizeof(float) * Bz * Hz,
                              sizeof(float) * (size_t)(Tz - 1) * Bz * Hz,
                              cudaMemcpyDeviceToDevice, 0);
}

// round 5
// speedup vs baseline: 4.0433x; 1.0469x over previous
#include <cuda_runtime.h>
#include <cstdint>

#define Bz 512
#define Iz 512
#define Hz 1024
#define Oz 512
#define Tz 128

// tcgen05 is arch-SPECIFIC (sm_103a). The harness also builds a generic
// compute_103 PTX pass where these instructions are illegal — guard them.
#if defined(__CUDA_ARCH__) && \
    (defined(__CUDA_ARCH_FEAT_SM103_ALL) || defined(__CUDA_ARCH_FEAT_SM100_ALL) || \
     defined(__CUDA_ARCH_SPECIFIC__))
#define HAS_TC5 1
#else
#define HAS_TC5 0
#endif

// --------------------------- device scratch ---------------------------------
__device__ float g_jx[Bz * Hz];                 // x@Wjx^T + bjx + bjh
__device__ float g_kx[Bz * Hz];                 // x@Wkx^T + bkx + bkh
__device__ float g_h0[Bz * Hz];
__device__ float g_hall[(size_t)Tz * Bz * Hz];  // all h_t (tf32-rounded), 256 MB
__device__ float g_Wjh[Hz * Hz];                // tf32-rounded weights
__device__ float g_Wkh[Hz * Hz];
__device__ float g_Wo[Oz * Hz];
__device__ unsigned g_bar[4][Tz];               // per-m-group, per-step barrier

// --------------------------- PTX helpers ------------------------------------
__device__ __forceinline__ uint32_t smem_u32(const void* p) {
    uint32_t a;
    asm("{ .reg .u64 t; cvta.to.shared.u64 t, %1; cvt.u32.u64 %0, t; }"
        : "=r"(a) : "l"(p));
    return a;
}
__device__ __forceinline__ float tf32r(float x) {
    uint32_t u; asm("cvt.rna.tf32.f32 %0, %1;" : "=r"(u) : "f"(x));
    return __uint_as_float(u);
}

#define CP16(dst, src) \
    asm volatile("cp.async.cg.shared.global [%0], [%1], 16;" :: "r"(dst), "l"(src) : "memory")
#define CPA_ARRIVE(mb) \
    asm volatile("cp.async.mbarrier.arrive.noinc.shared::cta.b64 [%0];" :: "r"(mb) : "memory")
#define FENCE_ASYNC() asm volatile("fence.proxy.async.shared::cta;" ::: "memory")

#define MBAR_INIT(mb, cnt) \
    asm volatile("mbarrier.init.shared.b64 [%0], %1;" :: "r"(mb), "r"((uint32_t)(cnt)) : "memory")
#define MBAR_INVAL(mb) \
    asm volatile("mbarrier.inval.shared.b64 [%0];" :: "r"(mb) : "memory")

#define MBAR_WAIT(mb, par) do {                                                  \
    uint32_t _m = (mb), _p = (par), _d;                                          \
    asm volatile("{\n\t.reg .pred p;\n\t"                                        \
        "mbarrier.try_wait.parity.acquire.cta.shared::cta.b64 p, [%1], %2;\n\t"  \
        "selp.b32 %0, 1, 0, p;\n\t}" : "=r"(_d) : "r"(_m), "r"(_p) : "memory");  \
    if (!_d) {                                                                   \
        asm volatile("{\n\t.reg .pred P1;\n\t"                                   \
        "WL_%=:\n\t"                                                             \
        "mbarrier.try_wait.parity.acquire.cta.shared::cta.b64 P1, [%0], %1, 0x989680;\n\t" \
        "@P1 bra.uni WD_%=;\n\t"                                                 \
        "bra.uni WL_%=;\n\t"                                                     \
        "WD_%=:\n\t}" :: "r"(_m), "r"(_p) : "memory");                           \
    }                                                                            \
} while (0)

// ---- tcgen05 wrappers (guarded) ----
__device__ __forceinline__ void tc_alloc(uint32_t sa, uint32_t n) {
#if HAS_TC5
    asm volatile("tcgen05.alloc.cta_group::1.sync.aligned.shared::cta.b32 [%0], %1;"
                 :: "r"(sa), "r"(n) : "memory");
    asm volatile("tcgen05.relinquish_alloc_permit.cta_group::1.sync.aligned;");
#endif
}
__device__ __forceinline__ void tc_dealloc(uint32_t t, uint32_t n) {
#if HAS_TC5
    asm volatile("tcgen05.dealloc.cta_group::1.sync.aligned.b32 %0, %1;" :: "r"(t), "r"(n));
#endif
}
__device__ __forceinline__ void tc_commit(uint32_t mb) {
#if HAS_TC5
    asm volatile("tcgen05.commit.cta_group::1.mbarrier::arrive::one.shared::cluster.b64 [%0];"
                 :: "r"(mb) : "memory");
#endif
}
__device__ __forceinline__ void tc_fence_after() {
#if HAS_TC5
    asm volatile("tcgen05.fence::after_thread_sync;" ::: "memory");
#endif
}
__device__ __forceinline__ void tc_wait_ld() {
#if HAS_TC5
    asm volatile("tcgen05.wait::ld.sync.aligned;" ::: "memory");
#endif
}
__device__ __forceinline__ void tc_ld32(uint32_t* r, uint32_t ta) {
#if HAS_TC5
    asm volatile("tcgen05.ld.sync.aligned.32x32b.x32.b32 "
        "{%0, %1, %2, %3, %4, %5, %6, %7, %8, %9, %10, %11, %12, %13, %14, %15,"
        " %16, %17, %18, %19, %20, %21, %22, %23, %24, %25, %26, %27, %28, %29, %30, %31}, [%32];"
        : "=r"(r[0]),  "=r"(r[1]),  "=r"(r[2]),  "=r"(r[3]),
          "=r"(r[4]),  "=r"(r[5]),  "=r"(r[6]),  "=r"(r[7]),
          "=r"(r[8]),  "=r"(r[9]),  "=r"(r[10]), "=r"(r[11]),
          "=r"(r[12]), "=r"(r[13]), "=r"(r[14]), "=r"(r[15]),
          "=r"(r[16]), "=r"(r[17]), "=r"(r[18]), "=r"(r[19]),
          "=r"(r[20]), "=r"(r[21]), "=r"(r[22]), "=r"(r[23]),
          "=r"(r[24]), "=r"(r[25]), "=r"(r[26]), "=r"(r[27]),
          "=r"(r[28]), "=r"(r[29]), "=r"(r[30]), "=r"(r[31])
        : "r"(ta));
#else
    #pragma unroll
    for (int i = 0; i < 32; ++i) r[i] = 0;
#endif
}
__device__ __forceinline__ void mma_tf32(uint32_t d, uint64_t ad, uint64_t bd,
                                         uint32_t idesc, uint32_t en) {
#if HAS_TC5
    asm volatile(
        "{\n\t.reg .pred p;\n\tsetp.ne.u32 p, %5, 0;\n\t"
        "tcgen05.mma.cta_group::1.kind::tf32 [%0], %1, %2, %3, {%4, %4, %4, %4}, p;\n\t}"
        :: "r"(d), "l"(ad), "l"(bd), "r"(idesc), "r"(0u), "r"(en) : "memory");
#endif
}

// SW128 K-major smem descriptor (LBO=1, SBO=64, version=1)
__device__ __forceinline__ uint64_t mkdesc(uint32_t addr) {
    constexpr uint64_t BASE =
        (2ull << 61) | (1ull << 46) | (64ull << 32) | (1ull << 16);
    return BASE | ((uint64_t)(addr >> 4) & 0x3FFF);
}

__device__ __forceinline__ float sigm(float x) {
    return 1.0f / (1.0f + __expf(-x));
}

// --------------------------- weight rounding --------------------------------
__global__ void round_weights(const float* __restrict__ Wjh,
                              const float* __restrict__ Wkh,
                              const float* __restrict__ Wo) {
    for (int i = blockIdx.x * blockDim.x + threadIdx.x; i < Hz * Hz;
         i += gridDim.x * blockDim.x) {
        g_Wjh[i] = tf32r(Wjh[i]);
        g_Wkh[i] = tf32r(Wkh[i]);
        if (i < Oz * Hz) g_Wo[i] = tf32r(Wo[i]);
    }
}

// ================= persistent recurrence kernel ==============================
// grid (16, 4): n-tile x m-tile = 64 CTAs (1/SM, co-resident). All T steps in
// one launch. Per step: 16 K-chunks of dual GEMM via ONE N=128 concatenated B
// tile (rows 0-63 = Wjh, 64-127 = Wkh) -> D cols [0,64)=j, [64,128)=k.
// Producer warps 0-7 (cp.async), MMA issuer tid 256. Steps separated by a
// per-m-group (16 CTA) device barrier on g_bar[group][t].
__global__ void __launch_bounds__(288, 1)
rec_persist() {
    constexpr int KC = 64;            // k per chunk
    constexpr int NC = Hz / KC;       // 16 chunks/step
    constexpr int S  = 3;             // pipeline stages
    constexpr uint32_t STG = 65536;   // A 32K + B 32K
    constexpr uint32_t OFF = 1024;
    constexpr uint32_t IDESC =        // M=128, N=128, tf32
        (8u << 24) | (16u << 17) | (2u << 10) | (2u << 7) | (1u << 4);

    extern __shared__ char smem[];
    const uint32_t sb = smem_u32(smem);
    const int tid = threadIdx.x;
    const int wid = tid >> 5, lid = tid & 31;
    const int m0 = blockIdx.y * 128;
    const int n0 = blockIdx.x * 64;
    const int grp = blockIdx.y;

    if (wid == 0) tc_alloc(sb + 0, 128);
    if (tid == 0) {
        #pragma unroll
        for (int s = 0; s < S; ++s) {
            MBAR_INIT(sb + 16 + 16 * s, 256);   // full[s]
            MBAR_INIT(sb + 24 + 16 * s, 1);     // empty[s]
        }
    }
    __syncthreads();
    uint32_t tb;
    asm volatile("ld.shared.b32 %0, [%1];" : "=r"(tb) : "r"(sb + 0));

    for (int t = 0; t < Tz; ++t) {
        const float* Ag = (t == 0) ? g_h0 : g_hall + (size_t)(t - 1) * Bz * Hz;

        if (tid < 256) {
            // ---------------- producers ----------------
            const float* Arow = Ag + (size_t)m0 * Hz;
            for (int c = 0; c < NC; ++c) {
                const int C = t * NC + c;
                const int s = C % S;
                if (C >= S) MBAR_WAIT(sb + 24 + 16 * s, ((C / S) - 1) & 1);
                const uint32_t base = sb + OFF + s * STG;
                const int k0 = c * KC;
                #pragma unroll
                for (int i = 0; i < 8; ++i) {             // A: 128 x 64 f32
                    int v = i * 256 + tid;
                    int row = v >> 4, kk = (v & 15) << 2;
                    uint32_t off = (uint32_t)(row << 7) + ((kk & 31) << 2);
                    off ^= (off >> 3) & 0x70;
                    CP16(base + (uint32_t)((kk >> 5) * 16384) + off,
                         Arow + (size_t)row * Hz + k0 + kk);
                }
                #pragma unroll
                for (int i = 0; i < 8; ++i) {             // B: 128 x 64 f32
                    int v = i * 256 + tid;
                    int row = v >> 4, kk = (v & 15) << 2;
                    uint32_t off = (uint32_t)(row << 7) + ((kk & 31) << 2);
                    off ^= (off >> 3) & 0x70;
                    uint32_t so = (uint32_t)((kk >> 5) * 16384) + off;
                    const float* src = (i < 4)
                        ? g_Wjh + (size_t)(n0 + row) * Hz + k0 + kk
                        : g_Wkh + (size_t)(n0 + row - 64) * Hz + k0 + kk;
                    CP16(base + 32768 + so, src);
                }
                CPA_ARRIVE(sb + 16 + 16 * s);
            }

            // ------------- epilogue (warps 0-7) -------------
            const int sub = wid & 3, wg = wid >> 2;
            const int m = m0 + sub * 32 + lid;
            const int n = n0 + wg * 32;
            const float4* jx4 = (const float4*)(g_jx + (size_t)m * Hz + n);
            const float4* kx4 = (const float4*)(g_kx + (size_t)m * Hz + n);
            const float4* hp4 = (const float4*)(Ag   + (size_t)m * Hz + n);
            // prefetch operands BEFORE the MMA-drain wait
            float4 jxv[8], kxv[8], hpv[8];
            #pragma unroll
            for (int v = 0; v < 8; ++v) { jxv[v] = jx4[v]; kxv[v] = kx4[v]; hpv[v] = hp4[v]; }

            const int CL = t * NC + (NC - 1);
            MBAR_WAIT(sb + 24 + 16 * (CL % S), (CL / S) & 1);
            tc_fence_after();

            uint32_t jr[32], kr[32];
            tc_ld32(jr, tb + wg * 32);
            tc_ld32(kr, tb + 64 + wg * 32);
            tc_wait_ld();

            float* hout = g_hall + (size_t)t * Bz * Hz;
            float4* ho4 = (float4*)(hout + (size_t)m * Hz + n);
            #pragma unroll
            for (int v = 0; v < 8; ++v) {
                float4 jx = jxv[v], kx = kxv[v], hp = hpv[v], o;
                {
                    float jg = sigm(jx.x + __uint_as_float(jr[4 * v + 0]));
                    float kg = sigm(kx.x + __uint_as_float(kr[4 * v + 0]));
                    o.x = tf32r(jg + hp.x * (1.0f - jg - kg));
                }
                {
                    float jg = sigm(jx.y + __uint_as_float(jr[4 * v + 1]));
                    float kg = sigm(kx.y + __uint_as_float(kr[4 * v + 1]));
                    o.y = tf32r(jg + hp.y * (1.0f - jg - kg));
                }
                {
                    float jg = sigm(jx.z + __uint_as_float(jr[4 * v + 2]));
                    float kg = sigm(kx.z + __uint_as_float(kr[4 * v + 2]));
                    o.z = tf32r(jg + hp.z * (1.0f - jg - kg));
                }
                {
                    float jg = sigm(jx.w + __uint_as_float(jr[4 * v + 3]));
                    float kg = sigm(kx.w + __uint_as_float(kr[4 * v + 3]));
                    o.w = tf32r(jg + hp.w * (1.0f - jg - kg));
                }
                ho4[v] = o;
            }
            __threadfence();
        } else if (tid == 256) {
            // ---------------- MMA issuer ----------------
            for (int c = 0; c < NC; ++c) {
                const int C = t * NC + c;
                const int s = C % S;
                MBAR_WAIT(sb + 16 + 16 * s, (C / S) & 1);
                FENCE_ASYNC();
                const uint32_t base = sb + OFF + s * STG;
                const uint64_t ad = mkdesc(base);
                const uint64_t bd = mkdesc(base + 32768);
                #pragma unroll
                for (int h = 0; h < 2; ++h)
                    #pragma unroll
                    for (int q = 0; q < 4; ++q) {
                        uint32_t en = (c | h | q) != 0;
                        mma_tf32(tb, ad + h * 1024 + q * 2,
                                 bd + h * 1024 + q * 2, IDESC, en);
                    }
                tc_commit(sb + 24 + 16 * s);
            }
        }

        // ---------------- per-step group barrier ----------------
        __syncthreads();    // epilogue stores + LDTMs done; TMEM reusable
        if (tid == 0) {
            unsigned* ctr = &g_bar[grp][t];
            asm volatile("red.release.gpu.global.add.u32 [%0], %1;"
                         :: "l"(ctr), "r"(1u) : "memory");
            unsigned v;
            do {
                asm volatile("ld.acquire.gpu.global.u32 %0, [%1];"
                             : "=r"(v) : "l"(ctr) : "memory");
                if (v < 16u) __nanosleep(64);
            } while (v < 16u);
        }
        __syncthreads();
    }

    // reset barrier counters for the next graph replay (all group members are
    // past every barrier at this point; each CTA owns 8 step slots)
    if (tid == 0) {
        #pragma unroll
        for (int k = 0; k < Tz / 16; ++k)
            g_bar[grp][blockIdx.x * (Tz / 16) + k] = 0;
        #pragma unroll
        for (int s = 0; s < S; ++s) {
            MBAR_INVAL(sb + 16 + 16 * s);
            MBAR_INVAL(sb + 24 + 16 * s);
        }
    }
    __syncthreads();
    if (wid == 0) tc_dealloc(tb, 128);
}

// ================= batched output GEMM (unchanged from R4) ===================
__global__ void __launch_bounds__(288, 1)
out_tc(const float* __restrict__ bo, float* __restrict__ outp) {
    constexpr int NT = 128;
    constexpr int KC = 64;
    constexpr int NC = Hz / KC;
    constexpr int S  = 3;
    constexpr uint32_t STG = 65536;
    constexpr uint32_t OFF = 1024;
    constexpr uint32_t IDESC =
        (8u << 24) | ((NT / 8) << 17) | (2u << 10) | (2u << 7) | (1u << 4);

    extern __shared__ char smem[];
    const uint32_t sb = smem_u32(smem);
    const int tid = threadIdx.x;
    const int wid = tid >> 5, lid = tid & 31;
    const int m0 = blockIdx.y * 128;
    const int n0 = blockIdx.x * NT;

    const float* Arow = g_hall + (size_t)m0 * Hz;

    if (wid == 0) tc_alloc(sb + 0, 128);
    if (tid == 0) {
        #pragma unroll
        for (int s = 0; s < S; ++s) {
            MBAR_INIT(sb + 16 + 16 * s, 256);
            MBAR_INIT(sb + 24 + 16 * s, 1);
        }
    }
    __syncthreads();
    uint32_t tb;
    asm volatile("ld.shared.b32 %0, [%1];" : "=r"(tb) : "r"(sb + 0));

    if (tid < 256) {
        for (int c = 0; c < NC; ++c) {
            const int s = c % S;
            if (c >= S) MBAR_WAIT(sb + 24 + 16 * s, ((c / S) - 1) & 1);
            const uint32_t base = sb + OFF + s * STG;
            const int k0 = c * KC;
            #pragma unroll
            for (int i = 0; i < 8; ++i) {
                int v = i * 256 + tid;
                int row = v >> 4, kk = (v & 15) << 2;
                uint32_t off = (uint32_t)(row << 7) + ((kk & 31) << 2);
                off ^= (off >> 3) & 0x70;
                CP16(base + (uint32_t)((kk >> 5) * 16384) + off,
                     Arow + (size_t)row * Hz + k0 + kk);
            }
            #pragma unroll
            for (int i = 0; i < 8; ++i) {
                int v = i * 256 + tid;
                int row = v >> 4, kk = (v & 15) << 2;
                uint32_t off = (uint32_t)(row << 7) + ((kk & 31) << 2);
                off ^= (off >> 3) & 0x70;
                uint32_t so = (uint32_t)((kk >> 5) * 16384) + off;
                CP16(base + 32768 + so, g_Wo + (size_t)(n0 + row) * Hz + k0 + kk);
            }
            CPA_ARRIVE(sb + 16 + 16 * s);
        }
    } else if (tid == 256) {
        for (int c = 0; c < NC; ++c) {
            const int s = c % S;
            MBAR_WAIT(sb + 16 + 16 * s, (c / S) & 1);
            FENCE_ASYNC();
            const uint32_t base = sb + OFF + s * STG;
            const uint64_t ad = mkdesc(base);
            const uint64_t bd = mkdesc(base + 32768);
            #pragma unroll
            for (int h = 0; h < 2; ++h)
                #pragma unroll
                for (int q = 0; q < 4; ++q) {
                    uint32_t en = (c | h | q) != 0;
                    mma_tf32(tb, ad + h * 1024 + q * 2,
                             bd + h * 1024 + q * 2, IDESC, en);
                }
            tc_commit(sb + 24 + 16 * s);
        }
    }

    MBAR_WAIT(sb + 24 + 16 * ((NC - 1) % S), ((NC - 1) / S) & 1);
    tc_fence_after();

    if (wid < 8) {
        const int sub = wid & 3, wg = wid >> 2;
        const int m = m0 + sub * 32 + lid;
        const int tt = m >> 9;
        const int bb = m & (Bz - 1);
        float* orow = outp + (size_t)bb * Tz * Oz + (size_t)tt * Oz;
        #pragma unroll
        for (int g = 0; g < 2; ++g) {
            const int nl = wg * 64 + g * 32;
            uint32_t r[32];
            tc_ld32(r, tb + nl);
            tc_wait_ld();
            const int n = n0 + nl;
            const float4* bo4 = (const float4*)(bo + n);
            float4* op = (float4*)(orow + n);
            #pragma unroll
            for (int v = 0; v < 8; ++v) {
                float4 b4 = bo4[v], o;
                o.x = __uint_as_float(r[4 * v + 0]) + b4.x;
                o.y = __uint_as_float(r[4 * v + 1]) + b4.y;
                o.z = __uint_as_float(r[4 * v + 2]) + b4.z;
                o.w = __uint_as_float(r[4 * v + 3]) + b4.w;
                op[v] = o;
            }
        }
    }

    __syncthreads();
    if (tid == 0) {
        #pragma unroll
        for (int s = 0; s < S; ++s) {
            MBAR_INVAL(sb + 16 + 16 * s);
            MBAR_INVAL(sb + 24 + 16 * s);
        }
    }
    __syncthreads();
    if (wid == 0) tc_dealloc(tb, 128);
}

// --------------------------- SIMT projection (once) -------------------------
__global__ void __launch_bounds__(256)
proj_gemm(const float* __restrict__ x,
          const float* __restrict__ W1, const float* __restrict__ W2,
          const float* __restrict__ b1a, const float* __restrict__ b1b,
          const float* __restrict__ b2a, const float* __restrict__ b2b) {
    constexpr int BM = 64, BN = 64, BK = 16, K = Iz;
    __shared__ float As[BK][BM + 4];
    __shared__ float W1s[BK][BN + 4];
    __shared__ float W2s[BK][BN + 4];

    const int tid = threadIdx.x;
    const int m0 = blockIdx.y * BM;
    const int n0 = blockIdx.x * BN;
    const int lr = tid >> 2;
    const int lk = (tid & 3) * 4;
    const int tmm = (tid & 15) * 4;
    const int tnn = (tid >> 4) * 4;

    float acc1[4][4] = {};
    float acc2[4][4] = {};

    for (int k0 = 0; k0 < K; k0 += BK) {
        float4 av = *(const float4*)(x  + (size_t)(m0 + lr) * K + k0 + lk);
        float4 w1 = *(const float4*)(W1 + (size_t)(n0 + lr) * K + k0 + lk);
        float4 w2 = *(const float4*)(W2 + (size_t)(n0 + lr) * K + k0 + lk);
        __syncthreads();
        As [lk + 0][lr] = av.x; As [lk + 1][lr] = av.y;
        As [lk + 2][lr] = av.z; As [lk + 3][lr] = av.w;
        W1s[lk + 0][lr] = w1.x; W1s[lk + 1][lr] = w1.y;
        W1s[lk + 2][lr] = w1.z; W1s[lk + 3][lr] = w1.w;
        W2s[lk + 0][lr] = w2.x; W2s[lk + 1][lr] = w2.y;
        W2s[lk + 2][lr] = w2.z; W2s[lk + 3][lr] = w2.w;
        __syncthreads();
        #pragma unroll
        for (int kk = 0; kk < BK; ++kk) {
            float a[4], u[4], v[4];
            #pragma unroll
            for (int i = 0; i < 4; ++i) a[i] = As[kk][tmm + i];
            #pragma unroll
            for (int j = 0; j < 4; ++j) { u[j] = W1s[kk][tnn + j]; v[j] = W2s[kk][tnn + j]; }
            #pragma unroll
            for (int i = 0; i < 4; ++i)
                #pragma unroll
                for (int j = 0; j < 4; ++j) {
                    acc1[i][j] = fmaf(a[i], u[j], acc1[i][j]);
                    acc2[i][j] = fmaf(a[i], v[j], acc2[i][j]);
                }
        }
    }

    #pragma unroll
    for (int i = 0; i < 4; ++i) {
        const int m = m0 + tmm + i;
        #pragma unroll
        for (int j = 0; j < 4; ++j) {
            const int n = n0 + tnn + j;
            const size_t idx = (size_t)m * Hz + n;
            g_jx[idx] = acc1[i][j] + b1a[n] + b1b[n];   // fold bjx + bjh
            g_kx[idx] = acc2[i][j] + b2a[n] + b2b[n];   // fold bkx + bkh
        }
    }
}

// --------------------------- host launcher ----------------------------------
extern "C" void kernel_launch(void* const* d_in, const int* in_sizes, int n_in,
                              void* d_out, int out_size) {
    const float* x   = (const float*)d_in[0];
    const float* h0  = (const float*)d_in[1];
    const float* Wjx = (const float*)d_in[2];
    const float* bjx = (const float*)d_in[3];
    const float* Wjh = (const float*)d_in[4];
    const float* bjh = (const float*)d_in[5];
    const float* Wkx = (const float*)d_in[6];
    const float* bkx = (const float*)d_in[7];
    const float* Wkh = (const float*)d_in[8];
    const float* bkh = (const float*)d_in[9];
    const float* Wo  = (const float*)d_in[10];
    const float* bo  = (const float*)d_in[11];
    float* out = (float*)d_out;

    cudaMemcpyToSymbolAsync(g_h0, h0, sizeof(float) * Bz * Hz, 0,
                            cudaMemcpyDeviceToDevice, 0);

    round_weights<<<512, 256>>>(Wjh, Wkh, Wo);
    proj_gemm<<<dim3(Hz / 64, Bz / 64), 256>>>(x, Wjx, Wkx, bjx, bjh, bkx, bkh);

    constexpr int SME = 1024 + 3 * 65536;   // 197632
    cudaFuncSetAttribute(rec_persist,
                         cudaFuncAttributeMaxDynamicSharedMemorySize, SME);
    cudaFuncSetAttribute(out_tc,
                         cudaFuncAttributeMaxDynamicSharedMemorySize, SME);

    // all 128 steps in one persistent launch (64 CTAs, 1/SM, co-resident)
    rec_persist<<<dim3(16, 4), 288, SME>>>();

    out_tc<<<dim3(Oz / 128, (Tz * Bz) / 128), 288, SME>>>(bo, out);

    cudaMemcpyFromSymbolAsync(out + (size_t)Bz * Tz * Oz, g_hall,
                              sizeof(float) * Bz * Hz,
                              sizeof(float) * (size_t)(Tz - 1) * Bz * Hz,
                              cudaMemcpyDeviceToDevice, 0);
}